// round 1
// baseline (speedup 1.0000x reference)
#include <cuda_runtime.h>
#include <cstdint>

namespace {

constexpr int B   = 1024;
constexpr int NP  = 22;
constexpr int DD  = 3;
constexpr int H   = 64;
constexpr int L   = 5;
constexpr int EPB = NP * (NP - 1);   // 462 directed edges per batch
constexpr int HS  = H + 1;           // padded stride (65): 65 % 32 == 1 -> conflict-free row gathers
constexpr int MS  = H + 1;
constexpr int NT  = 256;

// ---- shared weight region offsets (floats), edge-phase layout ----
constexpr int W_WE1  = 0;            // 130*64 = 8320
constexpr int W_WE2  = 8320;         // 64*64  = 4096
constexpr int W_WC1  = 12416;        // 64*64  = 4096
constexpr int W_WATT = 16512;        // 64
constexpr int W_WC2  = 16576;        // 64
constexpr int W_BE1  = 16640;        // 64
constexpr int W_BE2  = 16704;        // 64
constexpr int W_BC1  = 16768;        // 64
constexpr int W_BATT = 16832;        // 1 (+pad)
constexpr int W_SZ   = 16840;
// node-phase overlay (same region, reloaded each layer anyway)
constexpr int W_WN1 = 0;             // 128*64 = 8192
constexpr int W_WN2 = 8192;          // 64*64  = 4096
constexpr int W_BN1 = 12288;         // 64
constexpr int W_BN2 = 12352;         // 64

struct __align__(16) Smem {
  float W[W_SZ];              //  67,360 B  per-layer weights (union edge/node)
  float m[EPB * MS];          // 120,120 B  per-edge message m (stride-65 padded)
  float h[NP * HS];           //   5,720 B
  float agg[NP * HS];         //   5,720 B
  float coord[NP * DD];       //     264 B
  float ea[EPB];              //   1,848 B  fixed edge attr (initial sq-dist)
  float trans[EPB * DD];      //   5,544 B
  float scr[(NT / 32) * H];   //   2,048 B  per-warp node scratch
};                            // total ~208.6 KB

// ---------------- packed f32x2 helpers (Blackwell FFMA2 path) ----------------
__device__ __forceinline__ unsigned long long splat2(float v) {
  unsigned long long r;
  unsigned int u = __float_as_uint(v);
  asm("mov.b64 %0, {%1, %1};" : "=l"(r) : "r"(u));
  return r;
}
__device__ __forceinline__ unsigned long long pack2(float a, float b) {
  unsigned long long r;
  asm("mov.b64 %0, {%1, %2};" : "=l"(r) : "r"(__float_as_uint(a)), "r"(__float_as_uint(b)));
  return r;
}
__device__ __forceinline__ unsigned long long ffma2(unsigned long long a,
                                                    unsigned long long b,
                                                    unsigned long long c) {
  unsigned long long d;
  asm("fma.rn.f32x2 %0, %1, %2, %3;" : "=l"(d) : "l"(a), "l"(b), "l"(c));
  return d;
}
__device__ __forceinline__ void unpack2(unsigned long long v, float& lo, float& hi) {
  unsigned int a, b;
  asm("mov.b64 {%0, %1}, %2;" : "=r"(a), "=r"(b) : "l"(v));
  lo = __uint_as_float(a);
  hi = __uint_as_float(b);
}
__device__ __forceinline__ float silu_f(float x) {
  return __fdividef(x, 1.0f + __expf(-x));
}

// one k-step of a 64-wide GEMV: acc[0..31] (f32x2 pairs) += in * W[k][0..63]
__device__ __forceinline__ void gemv_row(unsigned long long acc[32],
                                         const ulonglong2* __restrict__ wrow,
                                         unsigned long long in2) {
#pragma unroll
  for (int i = 0; i < 16; i++) {
    ulonglong2 u = wrow[i];                 // LDS.128 broadcast (uniform addr)
    acc[2 * i]     = ffma2(in2, u.x, acc[2 * i]);
    acc[2 * i + 1] = ffma2(in2, u.y, acc[2 * i + 1]);
  }
}

__device__ __forceinline__ void cp_f4(float* dst, const float* __restrict__ src,
                                      int nfloats, int tid) {
  float4* d = reinterpret_cast<float4*>(dst);
  const float4* s = reinterpret_cast<const float4*>(src);
  for (int i = tid; i < (nfloats >> 2); i += NT) d[i] = s[i];
}

__global__ void __launch_bounds__(NT, 1)
egnn_kernel(const float* __restrict__ t, const float* __restrict__ x,
            const float* __restrict__ h_init,
            const float* __restrict__ Wemb, const float* __restrict__ bemb,
            const float* __restrict__ We1,  const float* __restrict__ be1,
            const float* __restrict__ We2,  const float* __restrict__ be2,
            const float* __restrict__ Watt, const float* __restrict__ batt,
            const float* __restrict__ Wn1,  const float* __restrict__ bn1,
            const float* __restrict__ Wn2,  const float* __restrict__ bn2,
            const float* __restrict__ Wc1,  const float* __restrict__ bc1,
            const float* __restrict__ Wc2,
            float* __restrict__ out)
{
  extern __shared__ char smem_raw[];
  Smem& s = *reinterpret_cast<Smem*>(smem_raw);
  const int b   = blockIdx.x;
  const int tid = threadIdx.x;

  // ---------- node embedding: h = [one_hot | t] @ Wemb + bemb ----------
  const float tb = t[b];
  for (int task = tid; task < NP * H; task += NT) {
    const int i = task / H, o = task % H;
    float acc = bemb[o] + tb * Wemb[NP * H + o];
#pragma unroll
    for (int j = 0; j < NP; j++) acc += h_init[i * NP + j] * Wemb[j * H + o];
    s.h[i * HS + o] = acc;
  }
  for (int task = tid; task < NP * DD; task += NT)
    s.coord[task] = x[b * (NP * DD) + task];
  __syncthreads();

  // fixed edge attribute from INITIAL coords
  for (int e = tid; e < EPB; e += NT) {
    const int r = e / (NP - 1), jj = e % (NP - 1);
    const int c = jj + (jj >= r ? 1 : 0);
    const float dx = s.coord[r * 3 + 0] - s.coord[c * 3 + 0];
    const float dy = s.coord[r * 3 + 1] - s.coord[c * 3 + 1];
    const float dz = s.coord[r * 3 + 2] - s.coord[c * 3 + 2];
    s.ea[e] = dx * dx + dy * dy + dz * dz;
  }

  for (int l = 0; l < L; l++) {
    // ---------- stage edge-phase weights ----------
    cp_f4(s.W + W_WE1,  We1 + l * 130 * H, 130 * H, tid);
    cp_f4(s.W + W_WE2,  We2 + l * H * H,   H * H,   tid);
    cp_f4(s.W + W_WC1,  Wc1 + l * H * H,   H * H,   tid);
    cp_f4(s.W + W_WATT, Watt + l * H,      H,       tid);
    cp_f4(s.W + W_WC2,  Wc2 + l * H,       H,       tid);
    cp_f4(s.W + W_BE1,  be1 + l * H,       H,       tid);
    cp_f4(s.W + W_BE2,  be2 + l * H,       H,       tid);
    cp_f4(s.W + W_BC1,  bc1 + l * H,       H,       tid);
    if (tid == 0) s.W[W_BATT] = batt[l];
    __syncthreads();

    // ---------- edge phase: thread-per-edge, full MLP chain ----------
#pragma unroll 1
    for (int e = tid; e < EPB; e += NT) {
      const int r = e / (NP - 1), jj = e % (NP - 1);
      const int c = jj + (jj >= r ? 1 : 0);
      const float dx = s.coord[r * 3 + 0] - s.coord[c * 3 + 0];
      const float dy = s.coord[r * 3 + 1] - s.coord[c * 3 + 1];
      const float dz = s.coord[r * 3 + 2] - s.coord[c * 3 + 2];
      const float radial = dx * dx + dy * dy + dz * dz;
      const float eav = s.ea[e];
      float* me = s.m + e * MS;

      unsigned long long acc[32];
      // m1 = silu([h_r | h_c | radial | ea] @ We1 + be1)
      {
        const unsigned long long* bp =
            reinterpret_cast<const unsigned long long*>(s.W + W_BE1);
#pragma unroll
        for (int i = 0; i < 32; i++) acc[i] = bp[i];
        const ulonglong2* W1 = reinterpret_cast<const ulonglong2*>(s.W + W_WE1);
        const float* hr = s.h + r * HS;
        const float* hc = s.h + c * HS;
#pragma unroll 2
        for (int k = 0; k < H; k++) gemv_row(acc, W1 + k * 16, splat2(hr[k]));
#pragma unroll 2
        for (int k = 0; k < H; k++) gemv_row(acc, W1 + (H + k) * 16, splat2(hc[k]));
        gemv_row(acc, W1 + 128 * 16, splat2(radial));
        gemv_row(acc, W1 + 129 * 16, splat2(eav));
#pragma unroll
        for (int i = 0; i < 32; i++) {
          float a, bv; unpack2(acc[i], a, bv);
          me[2 * i] = silu_f(a); me[2 * i + 1] = silu_f(bv);
        }
      }
      // m2 = silu(m1 @ We2 + be2); gated by sigmoid(m2 @ Watt + batt)
      float m2v[H];
      {
        const unsigned long long* bp =
            reinterpret_cast<const unsigned long long*>(s.W + W_BE2);
#pragma unroll
        for (int i = 0; i < 32; i++) acc[i] = bp[i];
        const ulonglong2* W2 = reinterpret_cast<const ulonglong2*>(s.W + W_WE2);
#pragma unroll 2
        for (int k = 0; k < H; k++) gemv_row(acc, W2 + k * 16, splat2(me[k]));
#pragma unroll
        for (int i = 0; i < 32; i++) {
          float a, bv; unpack2(acc[i], a, bv);
          m2v[2 * i] = silu_f(a); m2v[2 * i + 1] = silu_f(bv);
        }
        float attl = s.W[W_BATT];
#pragma unroll
        for (int o = 0; o < H; o++) attl += m2v[o] * s.W[W_WATT + o];
        const float sg = __fdividef(1.0f, 1.0f + __expf(-attl));
#pragma unroll
        for (int o = 0; o < H; o++) { m2v[o] *= sg; me[o] = m2v[o]; }
      }
      // phi = silu(m @ Wc1 + bc1) @ Wc2 ; trans = coord_diff * tanh(phi) * 3
      {
        const unsigned long long* bp =
            reinterpret_cast<const unsigned long long*>(s.W + W_BC1);
#pragma unroll
        for (int i = 0; i < 32; i++) acc[i] = bp[i];
        const ulonglong2* Wc = reinterpret_cast<const ulonglong2*>(s.W + W_WC1);
#pragma unroll 2
        for (int k = 0; k < H; k++) gemv_row(acc, Wc + k * 16, splat2(me[k]));
        float phi = 0.0f;
#pragma unroll
        for (int i = 0; i < 32; i++) {
          float a, bv; unpack2(acc[i], a, bv);
          phi += silu_f(a) * s.W[W_WC2 + 2 * i] + silu_f(bv) * s.W[W_WC2 + 2 * i + 1];
        }
        const float th = tanhf(phi) * 3.0f;  // COORDS_RANGE
        s.trans[e * 3 + 0] = dx * th;
        s.trans[e * 3 + 1] = dy * th;
        s.trans[e * 3 + 2] = dz * th;
      }
    }
    __syncthreads();

    // ---------- stage node weights (overlay) + segment-sum reductions ----------
    cp_f4(s.W + W_WN1, Wn1 + l * 128 * H, 128 * H, tid);
    cp_f4(s.W + W_WN2, Wn2 + l * H * H,   H * H,   tid);
    cp_f4(s.W + W_BN1, bn1 + l * H,       H,       tid);
    cp_f4(s.W + W_BN2, bn2 + l * H,       H,       tid);
    for (int task = tid; task < NP * H; task += NT) {
      const int r = task / H, o = task % H;
      const float* mp = s.m + (r * (NP - 1)) * MS + o;
      float a = 0.0f;
#pragma unroll
      for (int j = 0; j < NP - 1; j++) a += mp[j * MS];
      s.agg[r * HS + o] = a;
    }
    for (int task = tid; task < NP * DD; task += NT) {
      const int r = task / DD, d = task % DD;
      const float* tp = s.trans + (r * (NP - 1)) * DD + d;
      float a = 0.0f;
#pragma unroll
      for (int j = 0; j < NP - 1; j++) a += tp[j * DD];
      s.coord[task] += a;
    }
    __syncthreads();

    // ---------- node phase: warp-per-node, h += MLP([h | agg]) ----------
    {
      const int w = tid >> 5, lane = tid & 31;
      const unsigned long long* Wn1u =
          reinterpret_cast<const unsigned long long*>(s.W + W_WN1);
      const unsigned long long* Wn2u =
          reinterpret_cast<const unsigned long long*>(s.W + W_WN2);
      const unsigned long long bn1p =
          reinterpret_cast<const unsigned long long*>(s.W + W_BN1)[lane];
      const unsigned long long bn2p =
          reinterpret_cast<const unsigned long long*>(s.W + W_BN2)[lane];
      unsigned long long* scru = reinterpret_cast<unsigned long long*>(s.scr);
#pragma unroll 1
      for (int n = w; n < NP; n += NT / 32) {
        const float* hn = s.h + n * HS;
        const float* an = s.agg + n * HS;
        unsigned long long a1 = bn1p;
#pragma unroll 2
        for (int k = 0; k < H; k++) a1 = ffma2(splat2(hn[k]), Wn1u[k * 32 + lane], a1);
#pragma unroll 2
        for (int k = 0; k < H; k++) a1 = ffma2(splat2(an[k]), Wn1u[(H + k) * 32 + lane], a1);
        float lo, hi; unpack2(a1, lo, hi);
        scru[w * 32 + lane] = pack2(silu_f(lo), silu_f(hi));
        __syncwarp();
        const float* sc = s.scr + w * H;
        unsigned long long a2 = bn2p;
#pragma unroll 2
        for (int k = 0; k < H; k++) a2 = ffma2(splat2(sc[k]), Wn2u[k * 32 + lane], a2);
        unpack2(a2, lo, hi);
        s.h[n * HS + 2 * lane]     += lo;
        s.h[n * HS + 2 * lane + 1] += hi;
        __syncwarp();
      }
    }
    __syncthreads();
  }

  // ---------- output: vel = (coord - x) - mean_over_particles ----------
  if (tid < DD) {
    float mm = 0.0f;
    for (int i = 0; i < NP; i++)
      mm += s.coord[i * DD + tid] - x[b * (NP * DD) + i * DD + tid];
    s.ea[tid] = mm * (1.0f / NP);
  }
  __syncthreads();
  for (int task = tid; task < NP * DD; task += NT) {
    out[b * (NP * DD) + task] =
        (s.coord[task] - x[b * (NP * DD) + task]) - s.ea[task % DD];
  }
}

}  // namespace

extern "C" void kernel_launch(void* const* d_in, const int* in_sizes, int n_in,
                              void* d_out, int out_size) {
  (void)in_sizes; (void)n_in; (void)out_size;
  const float* t      = (const float*)d_in[0];
  const float* x      = (const float*)d_in[1];
  const float* h_init = (const float*)d_in[2];
  // d_in[3] rows / d_in[4] cols: fixed fully-connected pattern, derived analytically
  const float* Wemb = (const float*)d_in[5];
  const float* bemb = (const float*)d_in[6];
  const float* We1  = (const float*)d_in[7];
  const float* be1  = (const float*)d_in[8];
  const float* We2  = (const float*)d_in[9];
  const float* be2  = (const float*)d_in[10];
  const float* Watt = (const float*)d_in[11];
  const float* batt = (const float*)d_in[12];
  const float* Wn1  = (const float*)d_in[13];
  const float* bn1  = (const float*)d_in[14];
  const float* Wn2  = (const float*)d_in[15];
  const float* bn2  = (const float*)d_in[16];
  const float* Wc1  = (const float*)d_in[17];
  const float* bc1  = (const float*)d_in[18];
  const float* Wc2  = (const float*)d_in[19];

  cudaFuncSetAttribute(egnn_kernel, cudaFuncAttributeMaxDynamicSharedMemorySize,
                       (int)sizeof(Smem));
  egnn_kernel<<<B, NT, sizeof(Smem)>>>(t, x, h_init, Wemb, bemb, We1, be1, We2, be2,
                                       Watt, batt, Wn1, bn1, Wn2, bn2, Wc1, bc1, Wc2,
                                       (float*)d_out);
}

// round 2
// speedup vs baseline: 1.0832x; 1.0832x over previous
#include <cuda_runtime.h>
#include <cstdint>

namespace {

constexpr int B   = 1024;
constexpr int NP  = 22;
constexpr int DD  = 3;
constexpr int H   = 64;
constexpr int L   = 5;
constexpr int EPB = NP * (NP - 1);   // 462 directed edges per batch
constexpr int HS  = 68;              // h/agg stride: 16B-aligned rows, banks 4r+k -> warp-local conflict-free
constexpr int MS  = 65;              // m stride: conflict-free scalar row AND column access
constexpr int NT  = 480;             // 15 warps -> 3.75 warps/SMSP, 96% edge-lane efficiency

// ---- shared weight region offsets (floats), edge-phase layout ----
constexpr int W_WE1  = 0;            // 130*64 = 8320
constexpr int W_WE2  = 8320;         // 64*64  = 4096
constexpr int W_WC1  = 12416;        // 64*64  = 4096
constexpr int W_WATT = 16512;        // 64
constexpr int W_WC2  = 16576;        // 64
constexpr int W_BE1  = 16640;        // 64
constexpr int W_BE2  = 16704;        // 64
constexpr int W_BC1  = 16768;        // 64
constexpr int W_BATT = 16832;        // 1 (+pad)
constexpr int W_SZ   = 16840;
// node-phase overlay (same region, reloaded each layer anyway)
constexpr int W_WN1 = 0;             // 128*64 = 8192
constexpr int W_WN2 = 8192;          // 64*64  = 4096
constexpr int W_BN1 = 12288;         // 64
constexpr int W_BN2 = 12352;         // 64

struct __align__(16) Smem {
  float W[W_SZ];              //  67,360 B  per-layer weights (union edge/node)
  float h[NP * HS];           //   5,984 B  (16B-aligned rows)
  float agg[NP * HS];         //   5,984 B
  float m[EPB * MS];          // 120,120 B  ungated m2 per edge (stride-65)
  float gate[EPB];            //   1,848 B  sigmoid attention gate per edge
  float ea[EPB];              //   1,848 B  fixed edge attr (initial sq-dist)
  float trans[EPB * DD];      //   5,544 B
  float coord[NP * DD];       //     264 B
  float scr[(NT / 32) * H];   //   3,840 B  per-warp node scratch
};                            // ~212.8 KB

// ---------------- packed f32x2 helpers ----------------
__device__ __forceinline__ unsigned long long splat2(float v) {
  unsigned long long r;
  unsigned int u = __float_as_uint(v);
  asm("mov.b64 %0, {%1, %1};" : "=l"(r) : "r"(u));
  return r;
}
__device__ __forceinline__ unsigned long long pack2(float a, float b) {
  unsigned long long r;
  asm("mov.b64 %0, {%1, %2};" : "=l"(r) : "r"(__float_as_uint(a)), "r"(__float_as_uint(b)));
  return r;
}
__device__ __forceinline__ unsigned long long ffma2(unsigned long long a,
                                                    unsigned long long b,
                                                    unsigned long long c) {
  unsigned long long d;
  asm("fma.rn.f32x2 %0, %1, %2, %3;" : "=l"(d) : "l"(a), "l"(b), "l"(c));
  return d;
}
__device__ __forceinline__ void unpack2(unsigned long long v, float& lo, float& hi) {
  unsigned int a, b;
  asm("mov.b64 {%0, %1}, %2;" : "=r"(a), "=r"(b) : "l"(v));
  lo = __uint_as_float(a);
  hi = __uint_as_float(b);
}
__device__ __forceinline__ float silu_f(float x) {
  return __fdividef(x, 1.0f + __expf(-x));
}

// one k-step of a 32-wide half-GEMV: acc[0..15] (f32x2) += in * Wrow[half 32 floats]
__device__ __forceinline__ void ghalf(unsigned long long acc[16],
                                      const ulonglong2* __restrict__ wrow,
                                      unsigned long long in2) {
#pragma unroll
  for (int i = 0; i < 8; i++) {
    ulonglong2 u = wrow[i];                 // LDS.128 broadcast (uniform addr)
    acc[2 * i]     = ffma2(in2, u.x, acc[2 * i]);
    acc[2 * i + 1] = ffma2(in2, u.y, acc[2 * i + 1]);
  }
}

__device__ __forceinline__ void cp_f4(float* dst, const float* __restrict__ src,
                                      int nfloats, int tid) {
  float4* d = reinterpret_cast<float4*>(dst);
  const float4* s = reinterpret_cast<const float4*>(src);
  for (int i = tid; i < (nfloats >> 2); i += NT) d[i] = s[i];
}

__global__ void __launch_bounds__(NT, 1)
egnn_kernel(const float* __restrict__ t, const float* __restrict__ x,
            const float* __restrict__ h_init,
            const float* __restrict__ Wemb, const float* __restrict__ bemb,
            const float* __restrict__ We1,  const float* __restrict__ be1,
            const float* __restrict__ We2,  const float* __restrict__ be2,
            const float* __restrict__ Watt, const float* __restrict__ batt,
            const float* __restrict__ Wn1,  const float* __restrict__ bn1,
            const float* __restrict__ Wn2,  const float* __restrict__ bn2,
            const float* __restrict__ Wc1,  const float* __restrict__ bc1,
            const float* __restrict__ Wc2,
            float* __restrict__ out)
{
  extern __shared__ char smem_raw[];
  Smem& s = *reinterpret_cast<Smem*>(smem_raw);
  const int b   = blockIdx.x;
  const int tid = threadIdx.x;

  // ---------- node embedding: h = [one_hot | t] @ Wemb + bemb ----------
  const float tb = t[b];
  for (int task = tid; task < NP * H; task += NT) {
    const int i = task / H, o = task % H;
    float acc = bemb[o] + tb * Wemb[NP * H + o];
#pragma unroll
    for (int j = 0; j < NP; j++) acc += h_init[i * NP + j] * Wemb[j * H + o];
    s.h[i * HS + o] = acc;
  }
  for (int task = tid; task < NP * DD; task += NT)
    s.coord[task] = x[b * (NP * DD) + task];
  __syncthreads();

  // fixed edge attribute from INITIAL coords
  for (int e = tid; e < EPB; e += NT) {
    const int r = e / (NP - 1), jj = e % (NP - 1);
    const int c = jj + (jj >= r ? 1 : 0);
    const float dx = s.coord[r * 3 + 0] - s.coord[c * 3 + 0];
    const float dy = s.coord[r * 3 + 1] - s.coord[c * 3 + 1];
    const float dz = s.coord[r * 3 + 2] - s.coord[c * 3 + 2];
    s.ea[e] = dx * dx + dy * dy + dz * dz;
  }

  for (int l = 0; l < L; l++) {
    // ---------- stage edge-phase weights ----------
    cp_f4(s.W + W_WE1,  We1 + l * 130 * H, 130 * H, tid);
    cp_f4(s.W + W_WE2,  We2 + l * H * H,   H * H,   tid);
    cp_f4(s.W + W_WC1,  Wc1 + l * H * H,   H * H,   tid);
    cp_f4(s.W + W_WATT, Watt + l * H,      H,       tid);
    cp_f4(s.W + W_WC2,  Wc2 + l * H,       H,       tid);
    cp_f4(s.W + W_BE1,  be1 + l * H,       H,       tid);
    cp_f4(s.W + W_BE2,  be2 + l * H,       H,       tid);
    cp_f4(s.W + W_BC1,  bc1 + l * H,       H,       tid);
    if (tid == 0) s.W[W_BATT] = batt[l];
    __syncthreads();

    // ---------- edge phase: thread-per-edge, half-width GEMVs ----------
#pragma unroll 1
    for (int e = tid; e < EPB; e += NT) {
      const int r = e / (NP - 1), jj = e % (NP - 1);
      const int c = jj + (jj >= r ? 1 : 0);
      const float dx = s.coord[r * 3 + 0] - s.coord[c * 3 + 0];
      const float dy = s.coord[r * 3 + 1] - s.coord[c * 3 + 1];
      const float dz = s.coord[r * 3 + 2] - s.coord[c * 3 + 2];
      const float radial = dx * dx + dy * dy + dz * dz;
      const float eav = s.ea[e];
      float* me = s.m + e * MS;
      const float* hr = s.h + r * HS;   // 16B aligned
      const float* hc = s.h + c * HS;

      // ---- GEMV1: m1 = silu([h_r | h_c | radial | ea] @ We1 + be1), 2 halves ----
#pragma unroll 1
      for (int half = 0; half < 2; half++) {
        unsigned long long acc[16];
        const unsigned long long* bp =
            reinterpret_cast<const unsigned long long*>(s.W + W_BE1) + half * 16;
#pragma unroll
        for (int i = 0; i < 16; i++) acc[i] = bp[i];
        const ulonglong2* W1h =
            reinterpret_cast<const ulonglong2*>(s.W + W_WE1) + half * 8;
#pragma unroll 2
        for (int k0 = 0; k0 < H; k0 += 4) {
          const float4 hv = *reinterpret_cast<const float4*>(hr + k0);
          ghalf(acc, W1h + (k0 + 0) * 16, splat2(hv.x));
          ghalf(acc, W1h + (k0 + 1) * 16, splat2(hv.y));
          ghalf(acc, W1h + (k0 + 2) * 16, splat2(hv.z));
          ghalf(acc, W1h + (k0 + 3) * 16, splat2(hv.w));
        }
#pragma unroll 2
        for (int k0 = 0; k0 < H; k0 += 4) {
          const float4 hv = *reinterpret_cast<const float4*>(hc + k0);
          ghalf(acc, W1h + (H + k0 + 0) * 16, splat2(hv.x));
          ghalf(acc, W1h + (H + k0 + 1) * 16, splat2(hv.y));
          ghalf(acc, W1h + (H + k0 + 2) * 16, splat2(hv.z));
          ghalf(acc, W1h + (H + k0 + 3) * 16, splat2(hv.w));
        }
        ghalf(acc, W1h + 128 * 16, splat2(radial));
        ghalf(acc, W1h + 129 * 16, splat2(eav));
#pragma unroll
        for (int i = 0; i < 16; i++) {
          float a, bv; unpack2(acc[i], a, bv);
          me[half * 32 + 2 * i]     = silu_f(a);
          me[half * 32 + 2 * i + 1] = silu_f(bv);
        }
      }

      // ---- GEMV2: m2 = silu(m1 @ We2 + be2); att = m2 . Watt + batt ----
      unsigned long long m2[32];
      float att = s.W[W_BATT];
#pragma unroll 1
      for (int half = 0; half < 2; half++) {
        unsigned long long acc[16];
        const unsigned long long* bp =
            reinterpret_cast<const unsigned long long*>(s.W + W_BE2) + half * 16;
#pragma unroll
        for (int i = 0; i < 16; i++) acc[i] = bp[i];
        const ulonglong2* W2h =
            reinterpret_cast<const ulonglong2*>(s.W + W_WE2) + half * 8;
#pragma unroll 4
        for (int k = 0; k < H; k++) ghalf(acc, W2h + k * 16, splat2(me[k]));
#pragma unroll
        for (int i = 0; i < 16; i++) {
          float a, bv; unpack2(acc[i], a, bv);
          a = silu_f(a); bv = silu_f(bv);
          att += a  * s.W[W_WATT + half * 32 + 2 * i]
               + bv * s.W[W_WATT + half * 32 + 2 * i + 1];
          m2[half * 16 + i] = pack2(a, bv);
        }
      }
      const float sg = __fdividef(1.0f, 1.0f + __expf(-att));
      s.gate[e] = sg;                       // gate folded into agg + GEMVc input
#pragma unroll
      for (int i = 0; i < 32; i++) {        // store UNGATED m2
        float a, bv; unpack2(m2[i], a, bv);
        me[2 * i] = a; me[2 * i + 1] = bv;
      }

      // ---- GEMVc: phi = silu((m2*sg) @ Wc1 + bc1) . Wc2 ----
      float phi = 0.0f;
#pragma unroll 1
      for (int half = 0; half < 2; half++) {
        unsigned long long acc[16];
        const unsigned long long* bp =
            reinterpret_cast<const unsigned long long*>(s.W + W_BC1) + half * 16;
#pragma unroll
        for (int i = 0; i < 16; i++) acc[i] = bp[i];
        const ulonglong2* Wch =
            reinterpret_cast<const ulonglong2*>(s.W + W_WC1) + half * 8;
#pragma unroll 4
        for (int k = 0; k < H; k++) ghalf(acc, Wch + k * 16, splat2(me[k] * sg));
#pragma unroll
        for (int i = 0; i < 16; i++) {
          float a, bv; unpack2(acc[i], a, bv);
          phi += silu_f(a)  * s.W[W_WC2 + half * 32 + 2 * i]
               + silu_f(bv) * s.W[W_WC2 + half * 32 + 2 * i + 1];
        }
      }
      const float th = tanhf(phi) * 3.0f;   // COORDS_RANGE
      s.trans[e * 3 + 0] = dx * th;
      s.trans[e * 3 + 1] = dy * th;
      s.trans[e * 3 + 2] = dz * th;
    }
    __syncthreads();

    // ---------- stage node weights (overlay) + gated segment-sum ----------
    cp_f4(s.W + W_WN1, Wn1 + l * 128 * H, 128 * H, tid);
    cp_f4(s.W + W_WN2, Wn2 + l * H * H,   H * H,   tid);
    cp_f4(s.W + W_BN1, bn1 + l * H,       H,       tid);
    cp_f4(s.W + W_BN2, bn2 + l * H,       H,       tid);
    for (int task = tid; task < NP * H; task += NT) {
      const int r = task / H, o = task % H;
      const float* mp = s.m + (r * (NP - 1)) * MS + o;
      const float* gp = s.gate + r * (NP - 1);
      float a = 0.0f;
#pragma unroll
      for (int j = 0; j < NP - 1; j++) a = fmaf(gp[j], mp[j * MS], a);
      s.agg[r * HS + o] = a;
    }
    for (int task = tid; task < NP * DD; task += NT) {
      const int r = task / DD, d = task % DD;
      const float* tp = s.trans + (r * (NP - 1)) * DD + d;
      float a = 0.0f;
#pragma unroll
      for (int j = 0; j < NP - 1; j++) a += tp[j * DD];
      s.coord[task] += a;
    }
    __syncthreads();

    // ---------- node phase: warp-per-node, h += MLP([h | agg]) ----------
    {
      const int w = tid >> 5, lane = tid & 31;
      const unsigned long long* Wn1u =
          reinterpret_cast<const unsigned long long*>(s.W + W_WN1);
      const unsigned long long* Wn2u =
          reinterpret_cast<const unsigned long long*>(s.W + W_WN2);
      const unsigned long long bn1p =
          reinterpret_cast<const unsigned long long*>(s.W + W_BN1)[lane];
      const unsigned long long bn2p =
          reinterpret_cast<const unsigned long long*>(s.W + W_BN2)[lane];
      unsigned long long* scru = reinterpret_cast<unsigned long long*>(s.scr);
#pragma unroll 1
      for (int n = w; n < NP; n += NT / 32) {
        const float* hn = s.h + n * HS;
        const float* an = s.agg + n * HS;
        unsigned long long a1 = bn1p;
#pragma unroll 2
        for (int k = 0; k < H; k++) a1 = ffma2(splat2(hn[k]), Wn1u[k * 32 + lane], a1);
#pragma unroll 2
        for (int k = 0; k < H; k++) a1 = ffma2(splat2(an[k]), Wn1u[(H + k) * 32 + lane], a1);
        float lo, hi; unpack2(a1, lo, hi);
        scru[w * 32 + lane] = pack2(silu_f(lo), silu_f(hi));
        __syncwarp();
        const float* sc = s.scr + w * H;
        unsigned long long a2 = bn2p;
#pragma unroll 2
        for (int k = 0; k < H; k++) a2 = ffma2(splat2(sc[k]), Wn2u[k * 32 + lane], a2);
        unpack2(a2, lo, hi);
        s.h[n * HS + 2 * lane]     += lo;
        s.h[n * HS + 2 * lane + 1] += hi;
        __syncwarp();
      }
    }
    __syncthreads();
  }

  // ---------- output: vel = (coord - x) - mean_over_particles ----------
  if (tid < DD) {
    float mm = 0.0f;
    for (int i = 0; i < NP; i++)
      mm += s.coord[i * DD + tid] - x[b * (NP * DD) + i * DD + tid];
    s.ea[tid] = mm * (1.0f / NP);
  }
  __syncthreads();
  for (int task = tid; task < NP * DD; task += NT) {
    out[b * (NP * DD) + task] =
        (s.coord[task] - x[b * (NP * DD) + task]) - s.ea[task % DD];
  }
}

}  // namespace

extern "C" void kernel_launch(void* const* d_in, const int* in_sizes, int n_in,
                              void* d_out, int out_size) {
  (void)in_sizes; (void)n_in; (void)out_size;
  const float* t      = (const float*)d_in[0];
  const float* x      = (const float*)d_in[1];
  const float* h_init = (const float*)d_in[2];
  // d_in[3] rows / d_in[4] cols: fixed fully-connected pattern, derived analytically
  const float* Wemb = (const float*)d_in[5];
  const float* bemb = (const float*)d_in[6];
  const float* We1  = (const float*)d_in[7];
  const float* be1  = (const float*)d_in[8];
  const float* We2  = (const float*)d_in[9];
  const float* be2  = (const float*)d_in[10];
  const float* Watt = (const float*)d_in[11];
  const float* batt = (const float*)d_in[12];
  const float* Wn1  = (const float*)d_in[13];
  const float* bn1  = (const float*)d_in[14];
  const float* Wn2  = (const float*)d_in[15];
  const float* bn2  = (const float*)d_in[16];
  const float* Wc1  = (const float*)d_in[17];
  const float* bc1  = (const float*)d_in[18];
  const float* Wc2  = (const float*)d_in[19];

  cudaFuncSetAttribute(egnn_kernel, cudaFuncAttributeMaxDynamicSharedMemorySize,
                       (int)sizeof(Smem));
  egnn_kernel<<<B, NT, sizeof(Smem)>>>(t, x, h_init, Wemb, bemb, We1, be1, We2, be2,
                                       Watt, batt, Wn1, bn1, Wn2, bn2, Wc1, bc1, Wc2,
                                       (float*)d_out);
}

// round 3
// speedup vs baseline: 1.3263x; 1.2245x over previous
#include <cuda_runtime.h>
#include <cstdint>

namespace {

constexpr int B   = 1024;
constexpr int NP  = 22;
constexpr int DD  = 3;
constexpr int H   = 64;
constexpr int L   = 5;
constexpr int EPB = NP * (NP - 1);   // 462 directed edges per batch
constexpr int ND  = 231;             // dual-edge threads: t handles edges t and t+231
constexpr int HS  = 68;              // h/agg stride: 16B-aligned rows
constexpr int MS  = 65;              // m stride: conflict-free row AND column access
constexpr int NT  = 256;

// ---- shared weight region offsets (floats), edge-phase layout ----
constexpr int W_WE1  = 0;            // 130*64 = 8320
constexpr int W_WE2  = 8320;         // 64*64  = 4096
constexpr int W_WC1  = 12416;        // 64*64  = 4096
constexpr int W_WATT = 16512;        // 64
constexpr int W_WC2  = 16576;        // 64
constexpr int W_BE1  = 16640;        // 64
constexpr int W_BE2  = 16704;        // 64
constexpr int W_BC1  = 16768;        // 64
constexpr int W_BATT = 16832;        // 1 (+pad)
constexpr int W_SZ   = 16840;
// node-phase overlay
constexpr int W_WN1 = 0;             // 128*64 = 8192
constexpr int W_WN2 = 8192;          // 64*64  = 4096
constexpr int W_BN1 = 12288;
constexpr int W_BN2 = 12352;

struct __align__(16) Smem {
  float W[W_SZ];              //  67,360 B
  float h[NP * HS];           //   5,984 B
  float agg[NP * HS];         //   5,984 B
  float m[EPB * MS];          // 120,120 B  ungated m2 per edge
  float gate[EPB];            //   1,848 B
  float ea[EPB];              //   1,848 B
  float trans[EPB * DD];      //   5,544 B
  float coord[NP * DD];       //     264 B
  float scr[(NT / 32) * H];   //   2,048 B
};                            // ~211 KB

// ---------------- packed f32x2 helpers ----------------
__device__ __forceinline__ unsigned long long splat2(float v) {
  unsigned long long r;
  unsigned int u = __float_as_uint(v);
  asm("mov.b64 %0, {%1, %1};" : "=l"(r) : "r"(u));
  return r;
}
__device__ __forceinline__ unsigned long long pack2(float a, float b) {
  unsigned long long r;
  asm("mov.b64 %0, {%1, %2};" : "=l"(r) : "r"(__float_as_uint(a)), "r"(__float_as_uint(b)));
  return r;
}
__device__ __forceinline__ unsigned long long ffma2(unsigned long long a,
                                                    unsigned long long b,
                                                    unsigned long long c) {
  unsigned long long d;
  asm("fma.rn.f32x2 %0, %1, %2, %3;" : "=l"(d) : "l"(a), "l"(b), "l"(c));
  return d;
}
__device__ __forceinline__ void unpack2(unsigned long long v, float& lo, float& hi) {
  unsigned int a, b;
  asm("mov.b64 {%0, %1}, %2;" : "=r"(a), "=r"(b) : "l"(v));
  lo = __uint_as_float(a);
  hi = __uint_as_float(b);
}
__device__ __forceinline__ float silu_f(float x) {
  return __fdividef(x, 1.0f + __expf(-x));
}

// one k-step, 32-wide half-GEMV, TWO edges: each LDS.128 feeds 4 FFMA2
__device__ __forceinline__ void ghalf2(unsigned long long a0[16],
                                       unsigned long long a1[16],
                                       const ulonglong2* __restrict__ wrow,
                                       unsigned long long in0,
                                       unsigned long long in1) {
#pragma unroll
  for (int i = 0; i < 8; i++) {
    ulonglong2 u = wrow[i];                 // LDS.128 broadcast
    a0[2 * i]     = ffma2(in0, u.x, a0[2 * i]);
    a1[2 * i]     = ffma2(in1, u.x, a1[2 * i]);
    a0[2 * i + 1] = ffma2(in0, u.y, a0[2 * i + 1]);
    a1[2 * i + 1] = ffma2(in1, u.y, a1[2 * i + 1]);
  }
}

__device__ __forceinline__ void cp_f4(float* dst, const float* __restrict__ src,
                                      int nfloats, int tid) {
  float4* d = reinterpret_cast<float4*>(dst);
  const float4* s = reinterpret_cast<const float4*>(src);
  for (int i = tid; i < (nfloats >> 2); i += NT) d[i] = s[i];
}

__global__ void __launch_bounds__(NT, 1)
egnn_kernel(const float* __restrict__ t, const float* __restrict__ x,
            const float* __restrict__ h_init,
            const float* __restrict__ Wemb, const float* __restrict__ bemb,
            const float* __restrict__ We1,  const float* __restrict__ be1,
            const float* __restrict__ We2,  const float* __restrict__ be2,
            const float* __restrict__ Watt, const float* __restrict__ batt,
            const float* __restrict__ Wn1,  const float* __restrict__ bn1,
            const float* __restrict__ Wn2,  const float* __restrict__ bn2,
            const float* __restrict__ Wc1,  const float* __restrict__ bc1,
            const float* __restrict__ Wc2,
            float* __restrict__ out)
{
  extern __shared__ char smem_raw[];
  Smem& s = *reinterpret_cast<Smem*>(smem_raw);
  const int b   = blockIdx.x;
  const int tid = threadIdx.x;

  // ---------- node embedding: h = [one_hot | t] @ Wemb + bemb ----------
  const float tb = t[b];
  for (int task = tid; task < NP * H; task += NT) {
    const int i = task / H, o = task % H;
    float acc = bemb[o] + tb * Wemb[NP * H + o];
#pragma unroll
    for (int j = 0; j < NP; j++) acc += h_init[i * NP + j] * Wemb[j * H + o];
    s.h[i * HS + o] = acc;
  }
  for (int task = tid; task < NP * DD; task += NT)
    s.coord[task] = x[b * (NP * DD) + task];
  __syncthreads();

  // fixed edge attribute from INITIAL coords
  for (int e = tid; e < EPB; e += NT) {
    const int r = e / (NP - 1), jj = e % (NP - 1);
    const int c = jj + (jj >= r ? 1 : 0);
    const float dx = s.coord[r * 3 + 0] - s.coord[c * 3 + 0];
    const float dy = s.coord[r * 3 + 1] - s.coord[c * 3 + 1];
    const float dz = s.coord[r * 3 + 2] - s.coord[c * 3 + 2];
    s.ea[e] = dx * dx + dy * dy + dz * dz;
  }

  for (int l = 0; l < L; l++) {
    // ---------- stage edge-phase weights ----------
    cp_f4(s.W + W_WE1,  We1 + l * 130 * H, 130 * H, tid);
    cp_f4(s.W + W_WE2,  We2 + l * H * H,   H * H,   tid);
    cp_f4(s.W + W_WC1,  Wc1 + l * H * H,   H * H,   tid);
    cp_f4(s.W + W_WATT, Watt + l * H,      H,       tid);
    cp_f4(s.W + W_WC2,  Wc2 + l * H,       H,       tid);
    cp_f4(s.W + W_BE1,  be1 + l * H,       H,       tid);
    cp_f4(s.W + W_BE2,  be2 + l * H,       H,       tid);
    cp_f4(s.W + W_BC1,  bc1 + l * H,       H,       tid);
    if (tid == 0) s.W[W_BATT] = batt[l];
    __syncthreads();

    // ---------- edge phase: 2 edges per thread ----------
    if (tid < ND) {
      const int e0 = tid, e1 = tid + ND;
      const int r0 = e0 / (NP - 1), j0 = e0 % (NP - 1);
      const int c0 = j0 + (j0 >= r0 ? 1 : 0);
      const int r1 = e1 / (NP - 1), j1 = e1 % (NP - 1);
      const int c1 = j1 + (j1 >= r1 ? 1 : 0);
      const float dx0 = s.coord[r0 * 3 + 0] - s.coord[c0 * 3 + 0];
      const float dy0 = s.coord[r0 * 3 + 1] - s.coord[c0 * 3 + 1];
      const float dz0 = s.coord[r0 * 3 + 2] - s.coord[c0 * 3 + 2];
      const float dx1 = s.coord[r1 * 3 + 0] - s.coord[c1 * 3 + 0];
      const float dy1 = s.coord[r1 * 3 + 1] - s.coord[c1 * 3 + 1];
      const float dz1 = s.coord[r1 * 3 + 2] - s.coord[c1 * 3 + 2];
      const float rad0 = dx0 * dx0 + dy0 * dy0 + dz0 * dz0;
      const float rad1 = dx1 * dx1 + dy1 * dy1 + dz1 * dz1;
      const float ea0 = s.ea[e0], ea1 = s.ea[e1];
      float* me0 = s.m + e0 * MS;
      float* me1 = s.m + e1 * MS;
      const float* hr0 = s.h + r0 * HS;
      const float* hc0 = s.h + c0 * HS;
      const float* hr1 = s.h + r1 * HS;
      const float* hc1 = s.h + c1 * HS;

      // ---- GEMV1: m1 = silu([h_r | h_c | radial | ea] @ We1 + be1) ----
#pragma unroll 1
      for (int half = 0; half < 2; half++) {
        unsigned long long a0[16], a1[16];
        const unsigned long long* bp =
            reinterpret_cast<const unsigned long long*>(s.W + W_BE1) + half * 16;
#pragma unroll
        for (int i = 0; i < 16; i++) { a0[i] = bp[i]; a1[i] = bp[i]; }
        const ulonglong2* W1h =
            reinterpret_cast<const ulonglong2*>(s.W + W_WE1) + half * 8;
#pragma unroll 2
        for (int k0 = 0; k0 < H; k0 += 4) {
          const float4 v0 = *reinterpret_cast<const float4*>(hr0 + k0);
          const float4 v1 = *reinterpret_cast<const float4*>(hr1 + k0);
          ghalf2(a0, a1, W1h + (k0 + 0) * 16, splat2(v0.x), splat2(v1.x));
          ghalf2(a0, a1, W1h + (k0 + 1) * 16, splat2(v0.y), splat2(v1.y));
          ghalf2(a0, a1, W1h + (k0 + 2) * 16, splat2(v0.z), splat2(v1.z));
          ghalf2(a0, a1, W1h + (k0 + 3) * 16, splat2(v0.w), splat2(v1.w));
        }
#pragma unroll 2
        for (int k0 = 0; k0 < H; k0 += 4) {
          const float4 v0 = *reinterpret_cast<const float4*>(hc0 + k0);
          const float4 v1 = *reinterpret_cast<const float4*>(hc1 + k0);
          ghalf2(a0, a1, W1h + (H + k0 + 0) * 16, splat2(v0.x), splat2(v1.x));
          ghalf2(a0, a1, W1h + (H + k0 + 1) * 16, splat2(v0.y), splat2(v1.y));
          ghalf2(a0, a1, W1h + (H + k0 + 2) * 16, splat2(v0.z), splat2(v1.z));
          ghalf2(a0, a1, W1h + (H + k0 + 3) * 16, splat2(v0.w), splat2(v1.w));
        }
        ghalf2(a0, a1, W1h + 128 * 16, splat2(rad0), splat2(rad1));
        ghalf2(a0, a1, W1h + 129 * 16, splat2(ea0), splat2(ea1));
#pragma unroll
        for (int i = 0; i < 16; i++) {
          float p, q;
          unpack2(a0[i], p, q);
          me0[half * 32 + 2 * i] = silu_f(p);  me0[half * 32 + 2 * i + 1] = silu_f(q);
          unpack2(a1[i], p, q);
          me1[half * 32 + 2 * i] = silu_f(p);  me1[half * 32 + 2 * i + 1] = silu_f(q);
        }
      }

      // ---- GEMV2: m2 = silu(m1 @ We2 + be2); att = m2 . Watt + batt ----
      // Both halves must finish READING m1 (all 64 values) before m2
      // overwrites s.m — keep half-0 results in registers until the end.
      unsigned long long m2a[16], m2b[16];   // half-0 results, edges 0/1
      float att0 = s.W[W_BATT], att1 = att0;
#pragma unroll 1
      for (int half = 0; half < 2; half++) {
        unsigned long long a0[16], a1[16];
        const unsigned long long* bp =
            reinterpret_cast<const unsigned long long*>(s.W + W_BE2) + half * 16;
#pragma unroll
        for (int i = 0; i < 16; i++) { a0[i] = bp[i]; a1[i] = bp[i]; }
        const ulonglong2* W2h =
            reinterpret_cast<const ulonglong2*>(s.W + W_WE2) + half * 8;
#pragma unroll 4
        for (int k = 0; k < H; k++)
          ghalf2(a0, a1, W2h + k * 16, splat2(me0[k]), splat2(me1[k]));
#pragma unroll
        for (int i = 0; i < 16; i++) {
          float p, q;
          unpack2(a0[i], p, q);
          p = silu_f(p); q = silu_f(q);
          att0 += p * s.W[W_WATT + half * 32 + 2 * i]
                + q * s.W[W_WATT + half * 32 + 2 * i + 1];
          if (half == 0) m2a[i] = pack2(p, q);
          else { me0[32 + 2 * i] = p; me0[32 + 2 * i + 1] = q; }
          unpack2(a1[i], p, q);
          p = silu_f(p); q = silu_f(q);
          att1 += p * s.W[W_WATT + half * 32 + 2 * i]
                + q * s.W[W_WATT + half * 32 + 2 * i + 1];
          if (half == 0) m2b[i] = pack2(p, q);
          else { me1[32 + 2 * i] = p; me1[32 + 2 * i + 1] = q; }
        }
      }
      // now flush half-0 m2 (m1 low half no longer needed)
#pragma unroll
      for (int i = 0; i < 16; i++) {
        float p, q;
        unpack2(m2a[i], p, q); me0[2 * i] = p; me0[2 * i + 1] = q;
        unpack2(m2b[i], p, q); me1[2 * i] = p; me1[2 * i + 1] = q;
      }
      const float sg0 = __fdividef(1.0f, 1.0f + __expf(-att0));
      const float sg1 = __fdividef(1.0f, 1.0f + __expf(-att1));
      s.gate[e0] = sg0;
      s.gate[e1] = sg1;

      // ---- GEMVc: phi = silu((m2*sg) @ Wc1 + bc1) . Wc2 ----
      float phi0 = 0.0f, phi1 = 0.0f;
#pragma unroll 1
      for (int half = 0; half < 2; half++) {
        unsigned long long a0[16], a1[16];
        const unsigned long long* bp =
            reinterpret_cast<const unsigned long long*>(s.W + W_BC1) + half * 16;
#pragma unroll
        for (int i = 0; i < 16; i++) { a0[i] = bp[i]; a1[i] = bp[i]; }
        const ulonglong2* Wch =
            reinterpret_cast<const ulonglong2*>(s.W + W_WC1) + half * 8;
#pragma unroll 4
        for (int k = 0; k < H; k++)
          ghalf2(a0, a1, Wch + k * 16, splat2(me0[k] * sg0), splat2(me1[k] * sg1));
#pragma unroll
        for (int i = 0; i < 16; i++) {
          float p, q;
          unpack2(a0[i], p, q);
          phi0 += silu_f(p) * s.W[W_WC2 + half * 32 + 2 * i]
                + silu_f(q) * s.W[W_WC2 + half * 32 + 2 * i + 1];
          unpack2(a1[i], p, q);
          phi1 += silu_f(p) * s.W[W_WC2 + half * 32 + 2 * i]
                + silu_f(q) * s.W[W_WC2 + half * 32 + 2 * i + 1];
        }
      }
      const float th0 = tanhf(phi0) * 3.0f;   // COORDS_RANGE
      const float th1 = tanhf(phi1) * 3.0f;
      s.trans[e0 * 3 + 0] = dx0 * th0;
      s.trans[e0 * 3 + 1] = dy0 * th0;
      s.trans[e0 * 3 + 2] = dz0 * th0;
      s.trans[e1 * 3 + 0] = dx1 * th1;
      s.trans[e1 * 3 + 1] = dy1 * th1;
      s.trans[e1 * 3 + 2] = dz1 * th1;
    }
    __syncthreads();

    // ---------- stage node weights (overlay) + gated segment-sum ----------
    cp_f4(s.W + W_WN1, Wn1 + l * 128 * H, 128 * H, tid);
    cp_f4(s.W + W_WN2, Wn2 + l * H * H,   H * H,   tid);
    cp_f4(s.W + W_BN1, bn1 + l * H,       H,       tid);
    cp_f4(s.W + W_BN2, bn2 + l * H,       H,       tid);
    for (int task = tid; task < NP * H; task += NT) {
      const int r = task / H, o = task % H;
      const float* mp = s.m + (r * (NP - 1)) * MS + o;
      const float* gp = s.gate + r * (NP - 1);
      float a = 0.0f;
#pragma unroll
      for (int j = 0; j < NP - 1; j++) a = fmaf(gp[j], mp[j * MS], a);
      s.agg[r * HS + o] = a;
    }
    for (int task = tid; task < NP * DD; task += NT) {
      const int r = task / DD, d = task % DD;
      const float* tp = s.trans + (r * (NP - 1)) * DD + d;
      float a = 0.0f;
#pragma unroll
      for (int j = 0; j < NP - 1; j++) a += tp[j * DD];
      s.coord[task] += a;
    }
    __syncthreads();

    // ---------- node phase: warp-per-node, h += MLP([h | agg]) ----------
    {
      const int w = tid >> 5, lane = tid & 31;
      const unsigned long long* Wn1u =
          reinterpret_cast<const unsigned long long*>(s.W + W_WN1);
      const unsigned long long* Wn2u =
          reinterpret_cast<const unsigned long long*>(s.W + W_WN2);
      const unsigned long long bn1p =
          reinterpret_cast<const unsigned long long*>(s.W + W_BN1)[lane];
      const unsigned long long bn2p =
          reinterpret_cast<const unsigned long long*>(s.W + W_BN2)[lane];
      unsigned long long* scru = reinterpret_cast<unsigned long long*>(s.scr);
#pragma unroll 1
      for (int n = w; n < NP; n += NT / 32) {
        const float* hn = s.h + n * HS;
        const float* an = s.agg + n * HS;
        unsigned long long a1 = bn1p;
#pragma unroll 2
        for (int k = 0; k < H; k++) a1 = ffma2(splat2(hn[k]), Wn1u[k * 32 + lane], a1);
#pragma unroll 2
        for (int k = 0; k < H; k++) a1 = ffma2(splat2(an[k]), Wn1u[(H + k) * 32 + lane], a1);
        float lo, hi; unpack2(a1, lo, hi);
        scru[w * 32 + lane] = pack2(silu_f(lo), silu_f(hi));
        __syncwarp();
        const float* sc = s.scr + w * H;
        unsigned long long a2 = bn2p;
#pragma unroll 2
        for (int k = 0; k < H; k++) a2 = ffma2(splat2(sc[k]), Wn2u[k * 32 + lane], a2);
        unpack2(a2, lo, hi);
        s.h[n * HS + 2 * lane]     += lo;
        s.h[n * HS + 2 * lane + 1] += hi;
        __syncwarp();
      }
    }
    __syncthreads();
  }

  // ---------- output: vel = (coord - x) - mean_over_particles ----------
  if (tid < DD) {
    float mm = 0.0f;
    for (int i = 0; i < NP; i++)
      mm += s.coord[i * DD + tid] - x[b * (NP * DD) + i * DD + tid];
    s.ea[tid] = mm * (1.0f / NP);
  }
  __syncthreads();
  for (int task = tid; task < NP * DD; task += NT) {
    out[b * (NP * DD) + task] =
        (s.coord[task] - x[b * (NP * DD) + task]) - s.ea[task % DD];
  }
}

}  // namespace

extern "C" void kernel_launch(void* const* d_in, const int* in_sizes, int n_in,
                              void* d_out, int out_size) {
  (void)in_sizes; (void)n_in; (void)out_size;
  const float* t      = (const float*)d_in[0];
  const float* x      = (const float*)d_in[1];
  const float* h_init = (const float*)d_in[2];
  // d_in[3] rows / d_in[4] cols: fixed fully-connected pattern, derived analytically
  const float* Wemb = (const float*)d_in[5];
  const float* bemb = (const float*)d_in[6];
  const float* We1  = (const float*)d_in[7];
  const float* be1  = (const float*)d_in[8];
  const float* We2  = (const float*)d_in[9];
  const float* be2  = (const float*)d_in[10];
  const float* Watt = (const float*)d_in[11];
  const float* batt = (const float*)d_in[12];
  const float* Wn1  = (const float*)d_in[13];
  const float* bn1  = (const float*)d_in[14];
  const float* Wn2  = (const float*)d_in[15];
  const float* bn2  = (const float*)d_in[16];
  const float* Wc1  = (const float*)d_in[17];
  const float* bc1  = (const float*)d_in[18];
  const float* Wc2  = (const float*)d_in[19];

  cudaFuncSetAttribute(egnn_kernel, cudaFuncAttributeMaxDynamicSharedMemorySize,
                       (int)sizeof(Smem));
  egnn_kernel<<<B, NT, sizeof(Smem)>>>(t, x, h_init, Wemb, bemb, We1, be1, We2, be2,
                                       Watt, batt, Wn1, bn1, Wn2, bn2, Wc1, bc1, Wc2,
                                       (float*)d_out);
}

// round 4
// speedup vs baseline: 1.7934x; 1.3522x over previous
#include <cuda_runtime.h>
#include <cstdint>

namespace {

constexpr int B   = 1024;
constexpr int NP  = 22;
constexpr int DD  = 3;
constexpr int H   = 64;
constexpr int L   = 5;
constexpr int EPB = NP * (NP - 1);   // 462 directed edges per batch
constexpr int ND  = 231;             // dual-edge threads: t handles edges t and t+231
constexpr int HS  = 68;              // h/P/Q stride: 16B-aligned rows
constexpr int MS  = 65;              // m stride: conflict-free row AND column access
constexpr int NT  = 256;

// ---- shared weight region offsets (floats), edge-phase layout ----
constexpr int W_WE1  = 0;            // 130*64 = 8320 (full, for P/Q + rows 128/129)
constexpr int W_WE2  = 8320;         // 64*64  = 4096
constexpr int W_WC1  = 12416;        // 64*64  = 4096
constexpr int W_WATT = 16512;        // 64
constexpr int W_WC2  = 16576;        // 64
constexpr int W_BE1  = 16640;        // 64
constexpr int W_BE2  = 16704;        // 64
constexpr int W_BC1  = 16768;        // 64
constexpr int W_BATT = 16832;        // 1 (+pad)
constexpr int W_SZ   = 16840;
// node-phase overlay
constexpr int W_WN1 = 0;             // 128*64 = 8192
constexpr int W_WN2 = 8192;          // 64*64  = 4096
constexpr int W_BN1 = 12288;
constexpr int W_BN2 = 12352;

struct __align__(16) Smem {
  float W[W_SZ];              //  67,360 B
  float h[NP * HS];           //   5,984 B
  float P[NP * HS];           //   5,984 B  P_i = h_i @ We1[0:64]; reused as agg
  float Q[NP * HS];           //   5,984 B  Q_i = h_i @ We1[64:128]
  float m[EPB * MS];          // 120,120 B  m1 then ungated m2 per edge
  float gate[EPB];            //   1,848 B
  float ea[EPB];              //   1,848 B
  float trans[EPB * DD];      //   5,544 B
  float coord[NP * DD];       //     264 B
  float scr[(NT / 32) * H];   //   2,048 B
};                            // ~217 KB

// ---------------- packed f32x2 helpers ----------------
__device__ __forceinline__ unsigned long long splat2(float v) {
  unsigned long long r;
  unsigned int u = __float_as_uint(v);
  asm("mov.b64 %0, {%1, %1};" : "=l"(r) : "r"(u));
  return r;
}
__device__ __forceinline__ unsigned long long pack2(float a, float b) {
  unsigned long long r;
  asm("mov.b64 %0, {%1, %2};" : "=l"(r) : "r"(__float_as_uint(a)), "r"(__float_as_uint(b)));
  return r;
}
__device__ __forceinline__ unsigned long long ffma2(unsigned long long a,
                                                    unsigned long long b,
                                                    unsigned long long c) {
  unsigned long long d;
  asm("fma.rn.f32x2 %0, %1, %2, %3;" : "=l"(d) : "l"(a), "l"(b), "l"(c));
  return d;
}
__device__ __forceinline__ void unpack2(unsigned long long v, float& lo, float& hi) {
  unsigned int a, b;
  asm("mov.b64 {%0, %1}, %2;" : "=r"(a), "=r"(b) : "l"(v));
  lo = __uint_as_float(a);
  hi = __uint_as_float(b);
}
__device__ __forceinline__ float silu_f(float x) {
  return __fdividef(x, 1.0f + __expf(-x));
}

// one k-step, 32-wide half-GEMV, TWO edges: each LDS.128 feeds 4 FFMA2
__device__ __forceinline__ void ghalf2(unsigned long long a0[16],
                                       unsigned long long a1[16],
                                       const ulonglong2* __restrict__ wrow,
                                       unsigned long long in0,
                                       unsigned long long in1) {
#pragma unroll
  for (int i = 0; i < 8; i++) {
    ulonglong2 u = wrow[i];                 // LDS.128 broadcast
    a0[2 * i]     = ffma2(in0, u.x, a0[2 * i]);
    a1[2 * i]     = ffma2(in1, u.x, a1[2 * i]);
    a0[2 * i + 1] = ffma2(in0, u.y, a0[2 * i + 1]);
    a1[2 * i + 1] = ffma2(in1, u.y, a1[2 * i + 1]);
  }
}

__device__ __forceinline__ void cp_f4(float* dst, const float* __restrict__ src,
                                      int nfloats, int tid) {
  float4* d = reinterpret_cast<float4*>(dst);
  const float4* s = reinterpret_cast<const float4*>(src);
  for (int i = tid; i < (nfloats >> 2); i += NT) d[i] = s[i];
}

__global__ void __launch_bounds__(NT, 1)
egnn_kernel(const float* __restrict__ t, const float* __restrict__ x,
            const float* __restrict__ h_init,
            const float* __restrict__ Wemb, const float* __restrict__ bemb,
            const float* __restrict__ We1,  const float* __restrict__ be1,
            const float* __restrict__ We2,  const float* __restrict__ be2,
            const float* __restrict__ Watt, const float* __restrict__ batt,
            const float* __restrict__ Wn1,  const float* __restrict__ bn1,
            const float* __restrict__ Wn2,  const float* __restrict__ bn2,
            const float* __restrict__ Wc1,  const float* __restrict__ bc1,
            const float* __restrict__ Wc2,
            float* __restrict__ out)
{
  extern __shared__ char smem_raw[];
  Smem& s = *reinterpret_cast<Smem*>(smem_raw);
  const int b   = blockIdx.x;
  const int tid = threadIdx.x;

  // ---------- node embedding: h = [one_hot | t] @ Wemb + bemb ----------
  const float tb = t[b];
  for (int task = tid; task < NP * H; task += NT) {
    const int i = task / H, o = task % H;
    float acc = bemb[o] + tb * Wemb[NP * H + o];
#pragma unroll
    for (int j = 0; j < NP; j++) acc += h_init[i * NP + j] * Wemb[j * H + o];
    s.h[i * HS + o] = acc;
  }
  for (int task = tid; task < NP * DD; task += NT)
    s.coord[task] = x[b * (NP * DD) + task];
  __syncthreads();

  // fixed edge attribute from INITIAL coords
  for (int e = tid; e < EPB; e += NT) {
    const int r = e / (NP - 1), jj = e % (NP - 1);
    const int c = jj + (jj >= r ? 1 : 0);
    const float dx = s.coord[r * 3 + 0] - s.coord[c * 3 + 0];
    const float dy = s.coord[r * 3 + 1] - s.coord[c * 3 + 1];
    const float dz = s.coord[r * 3 + 2] - s.coord[c * 3 + 2];
    s.ea[e] = dx * dx + dy * dy + dz * dz;
  }

  for (int l = 0; l < L; l++) {
    // ---------- stage edge-phase weights ----------
    cp_f4(s.W + W_WE1,  We1 + l * 130 * H, 130 * H, tid);
    cp_f4(s.W + W_WE2,  We2 + l * H * H,   H * H,   tid);
    cp_f4(s.W + W_WC1,  Wc1 + l * H * H,   H * H,   tid);
    cp_f4(s.W + W_WATT, Watt + l * H,      H,       tid);
    cp_f4(s.W + W_WC2,  Wc2 + l * H,       H,       tid);
    cp_f4(s.W + W_BE1,  be1 + l * H,       H,       tid);
    cp_f4(s.W + W_BE2,  be2 + l * H,       H,       tid);
    cp_f4(s.W + W_BC1,  bc1 + l * H,       H,       tid);
    if (tid == 0) s.W[W_BATT] = batt[l];
    __syncthreads();

    // ---------- P/Q phase: warp-per-node ----------
    // P_i = h_i @ We1[0:64,:],  Q_i = h_i @ We1[64:128,:]
    {
      const int w = tid >> 5, lane = tid & 31;
      const unsigned long long* W1u =
          reinterpret_cast<const unsigned long long*>(s.W + W_WE1);  // [130][32 pairs]
#pragma unroll 1
      for (int n = w; n < NP; n += NT / 32) {
        const float* hn = s.h + n * HS;
        unsigned long long accP = 0ull, accQ = 0ull;
#pragma unroll 4
        for (int k = 0; k < H; k++) {
          const unsigned long long hv = splat2(hn[k]);
          accP = ffma2(hv, W1u[k * 32 + lane], accP);
          accQ = ffma2(hv, W1u[(H + k) * 32 + lane], accQ);
        }
        reinterpret_cast<unsigned long long*>(s.P + n * HS)[lane] = accP;
        reinterpret_cast<unsigned long long*>(s.Q + n * HS)[lane] = accQ;
      }
    }
    __syncthreads();

    // ---------- edge phase: 2 edges per thread ----------
    if (tid < ND) {
      const int e0 = tid, e1 = tid + ND;
      const int r0 = e0 / (NP - 1), j0 = e0 % (NP - 1);
      const int c0 = j0 + (j0 >= r0 ? 1 : 0);
      const int r1 = e1 / (NP - 1), j1 = e1 % (NP - 1);
      const int c1 = j1 + (j1 >= r1 ? 1 : 0);
      const float dx0 = s.coord[r0 * 3 + 0] - s.coord[c0 * 3 + 0];
      const float dy0 = s.coord[r0 * 3 + 1] - s.coord[c0 * 3 + 1];
      const float dz0 = s.coord[r0 * 3 + 2] - s.coord[c0 * 3 + 2];
      const float dx1 = s.coord[r1 * 3 + 0] - s.coord[c1 * 3 + 0];
      const float dy1 = s.coord[r1 * 3 + 1] - s.coord[c1 * 3 + 1];
      const float dz1 = s.coord[r1 * 3 + 2] - s.coord[c1 * 3 + 2];
      const float rad0 = dx0 * dx0 + dy0 * dy0 + dz0 * dz0;
      const float rad1 = dx1 * dx1 + dy1 * dy1 + dz1 * dz1;
      const float ea0 = s.ea[e0], ea1 = s.ea[e1];
      float* me0 = s.m + e0 * MS;
      float* me1 = s.m + e1 * MS;

      // ---- m1 assembly: m1 = silu(P_r + Q_c + rad*We1[128] + ea*We1[129] + be1) ----
      {
        const float* Pr0 = s.P + r0 * HS;
        const float* Qc0 = s.Q + c0 * HS;
        const float* Pr1 = s.P + r1 * HS;
        const float* Qc1 = s.Q + c1 * HS;
        const float* wr  = s.W + W_WE1 + 128 * H;   // radial row
        const float* we  = s.W + W_WE1 + 129 * H;   // edge-attr row
        const float* bb  = s.W + W_BE1;
#pragma unroll
        for (int o = 0; o < H; o += 4) {
          const float4 p0 = *reinterpret_cast<const float4*>(Pr0 + o);
          const float4 q0 = *reinterpret_cast<const float4*>(Qc0 + o);
          const float4 p1 = *reinterpret_cast<const float4*>(Pr1 + o);
          const float4 q1 = *reinterpret_cast<const float4*>(Qc1 + o);
          const float4 wv = *reinterpret_cast<const float4*>(wr + o);
          const float4 ev = *reinterpret_cast<const float4*>(we + o);
          const float4 bv = *reinterpret_cast<const float4*>(bb + o);
          me0[o + 0] = silu_f(p0.x + q0.x + rad0 * wv.x + ea0 * ev.x + bv.x);
          me0[o + 1] = silu_f(p0.y + q0.y + rad0 * wv.y + ea0 * ev.y + bv.y);
          me0[o + 2] = silu_f(p0.z + q0.z + rad0 * wv.z + ea0 * ev.z + bv.z);
          me0[o + 3] = silu_f(p0.w + q0.w + rad0 * wv.w + ea0 * ev.w + bv.w);
          me1[o + 0] = silu_f(p1.x + q1.x + rad1 * wv.x + ea1 * ev.x + bv.x);
          me1[o + 1] = silu_f(p1.y + q1.y + rad1 * wv.y + ea1 * ev.y + bv.y);
          me1[o + 2] = silu_f(p1.z + q1.z + rad1 * wv.z + ea1 * ev.z + bv.z);
          me1[o + 3] = silu_f(p1.w + q1.w + rad1 * wv.w + ea1 * ev.w + bv.w);
        }
      }

      // ---- GEMV2: m2 = silu(m1 @ We2 + be2); att = m2 . Watt + batt ----
      // Keep half-0 m2 in registers until all m1 reads complete.
      unsigned long long m2a[16], m2b[16];
      float att0 = s.W[W_BATT], att1 = att0;
#pragma unroll 1
      for (int half = 0; half < 2; half++) {
        unsigned long long a0[16], a1[16];
        const unsigned long long* bp =
            reinterpret_cast<const unsigned long long*>(s.W + W_BE2) + half * 16;
#pragma unroll
        for (int i = 0; i < 16; i++) { a0[i] = bp[i]; a1[i] = bp[i]; }
        const ulonglong2* W2h =
            reinterpret_cast<const ulonglong2*>(s.W + W_WE2) + half * 8;
#pragma unroll 4
        for (int k = 0; k < H; k++)
          ghalf2(a0, a1, W2h + k * 16, splat2(me0[k]), splat2(me1[k]));
#pragma unroll
        for (int i = 0; i < 16; i++) {
          float p, q;
          unpack2(a0[i], p, q);
          p = silu_f(p); q = silu_f(q);
          att0 += p * s.W[W_WATT + half * 32 + 2 * i]
                + q * s.W[W_WATT + half * 32 + 2 * i + 1];
          if (half == 0) m2a[i] = pack2(p, q);
          else { me0[32 + 2 * i] = p; me0[32 + 2 * i + 1] = q; }
          unpack2(a1[i], p, q);
          p = silu_f(p); q = silu_f(q);
          att1 += p * s.W[W_WATT + half * 32 + 2 * i]
                + q * s.W[W_WATT + half * 32 + 2 * i + 1];
          if (half == 0) m2b[i] = pack2(p, q);
          else { me1[32 + 2 * i] = p; me1[32 + 2 * i + 1] = q; }
        }
      }
#pragma unroll
      for (int i = 0; i < 16; i++) {
        float p, q;
        unpack2(m2a[i], p, q); me0[2 * i] = p; me0[2 * i + 1] = q;
        unpack2(m2b[i], p, q); me1[2 * i] = p; me1[2 * i + 1] = q;
      }
      const float sg0 = __fdividef(1.0f, 1.0f + __expf(-att0));
      const float sg1 = __fdividef(1.0f, 1.0f + __expf(-att1));
      s.gate[e0] = sg0;
      s.gate[e1] = sg1;

      // ---- GEMVc: phi = silu((m2*sg) @ Wc1 + bc1) . Wc2 ----
      float phi0 = 0.0f, phi1 = 0.0f;
#pragma unroll 1
      for (int half = 0; half < 2; half++) {
        unsigned long long a0[16], a1[16];
        const unsigned long long* bp =
            reinterpret_cast<const unsigned long long*>(s.W + W_BC1) + half * 16;
#pragma unroll
        for (int i = 0; i < 16; i++) { a0[i] = bp[i]; a1[i] = bp[i]; }
        const ulonglong2* Wch =
            reinterpret_cast<const ulonglong2*>(s.W + W_WC1) + half * 8;
#pragma unroll 4
        for (int k = 0; k < H; k++)
          ghalf2(a0, a1, Wch + k * 16, splat2(me0[k] * sg0), splat2(me1[k] * sg1));
#pragma unroll
        for (int i = 0; i < 16; i++) {
          float p, q;
          unpack2(a0[i], p, q);
          phi0 += silu_f(p) * s.W[W_WC2 + half * 32 + 2 * i]
                + silu_f(q) * s.W[W_WC2 + half * 32 + 2 * i + 1];
          unpack2(a1[i], p, q);
          phi1 += silu_f(p) * s.W[W_WC2 + half * 32 + 2 * i]
                + silu_f(q) * s.W[W_WC2 + half * 32 + 2 * i + 1];
        }
      }
      const float th0 = tanhf(phi0) * 3.0f;   // COORDS_RANGE
      const float th1 = tanhf(phi1) * 3.0f;
      s.trans[e0 * 3 + 0] = dx0 * th0;
      s.trans[e0 * 3 + 1] = dy0 * th0;
      s.trans[e0 * 3 + 2] = dz0 * th0;
      s.trans[e1 * 3 + 0] = dx1 * th1;
      s.trans[e1 * 3 + 1] = dy1 * th1;
      s.trans[e1 * 3 + 2] = dz1 * th1;
    }
    __syncthreads();

    // ---------- stage node weights (overlay) + gated segment-sum ----------
    cp_f4(s.W + W_WN1, Wn1 + l * 128 * H, 128 * H, tid);
    cp_f4(s.W + W_WN2, Wn2 + l * H * H,   H * H,   tid);
    cp_f4(s.W + W_BN1, bn1 + l * H,       H,       tid);
    cp_f4(s.W + W_BN2, bn2 + l * H,       H,       tid);
    for (int task = tid; task < NP * H; task += NT) {
      const int r = task / H, o = task % H;
      const float* mp = s.m + (r * (NP - 1)) * MS + o;
      const float* gp = s.gate + r * (NP - 1);
      float a = 0.0f;
#pragma unroll
      for (int j = 0; j < NP - 1; j++) a = fmaf(gp[j], mp[j * MS], a);
      s.P[r * HS + o] = a;                  // agg (reuses P buffer)
    }
    for (int task = tid; task < NP * DD; task += NT) {
      const int r = task / DD, d = task % DD;
      const float* tp = s.trans + (r * (NP - 1)) * DD + d;
      float a = 0.0f;
#pragma unroll
      for (int j = 0; j < NP - 1; j++) a += tp[j * DD];
      s.coord[task] += a;
    }
    __syncthreads();

    // ---------- node phase: warp-per-node, h += MLP([h | agg]) ----------
    {
      const int w = tid >> 5, lane = tid & 31;
      const unsigned long long* Wn1u =
          reinterpret_cast<const unsigned long long*>(s.W + W_WN1);
      const unsigned long long* Wn2u =
          reinterpret_cast<const unsigned long long*>(s.W + W_WN2);
      const unsigned long long bn1p =
          reinterpret_cast<const unsigned long long*>(s.W + W_BN1)[lane];
      const unsigned long long bn2p =
          reinterpret_cast<const unsigned long long*>(s.W + W_BN2)[lane];
      unsigned long long* scru = reinterpret_cast<unsigned long long*>(s.scr);
#pragma unroll 1
      for (int n = w; n < NP; n += NT / 32) {
        const float* hn = s.h + n * HS;
        const float* an = s.P + n * HS;     // agg
        unsigned long long a1 = bn1p;
#pragma unroll 2
        for (int k = 0; k < H; k++) a1 = ffma2(splat2(hn[k]), Wn1u[k * 32 + lane], a1);
#pragma unroll 2
        for (int k = 0; k < H; k++) a1 = ffma2(splat2(an[k]), Wn1u[(H + k) * 32 + lane], a1);
        float lo, hi; unpack2(a1, lo, hi);
        scru[w * 32 + lane] = pack2(silu_f(lo), silu_f(hi));
        __syncwarp();
        const float* sc = s.scr + w * H;
        unsigned long long a2 = bn2p;
#pragma unroll 2
        for (int k = 0; k < H; k++) a2 = ffma2(splat2(sc[k]), Wn2u[k * 32 + lane], a2);
        unpack2(a2, lo, hi);
        s.h[n * HS + 2 * lane]     += lo;
        s.h[n * HS + 2 * lane + 1] += hi;
        __syncwarp();
      }
    }
    __syncthreads();
  }

  // ---------- output: vel = (coord - x) - mean_over_particles ----------
  if (tid < DD) {
    float mm = 0.0f;
    for (int i = 0; i < NP; i++)
      mm += s.coord[i * DD + tid] - x[b * (NP * DD) + i * DD + tid];
    s.ea[tid] = mm * (1.0f / NP);
  }
  __syncthreads();
  for (int task = tid; task < NP * DD; task += NT) {
    out[b * (NP * DD) + task] =
        (s.coord[task] - x[b * (NP * DD) + task]) - s.ea[task % DD];
  }
}

}  // namespace

extern "C" void kernel_launch(void* const* d_in, const int* in_sizes, int n_in,
                              void* d_out, int out_size) {
  (void)in_sizes; (void)n_in; (void)out_size;
  const float* t      = (const float*)d_in[0];
  const float* x      = (const float*)d_in[1];
  const float* h_init = (const float*)d_in[2];
  // d_in[3] rows / d_in[4] cols: fixed fully-connected pattern, derived analytically
  const float* Wemb = (const float*)d_in[5];
  const float* bemb = (const float*)d_in[6];
  const float* We1  = (const float*)d_in[7];
  const float* be1  = (const float*)d_in[8];
  const float* We2  = (const float*)d_in[9];
  const float* be2  = (const float*)d_in[10];
  const float* Watt = (const float*)d_in[11];
  const float* batt = (const float*)d_in[12];
  const float* Wn1  = (const float*)d_in[13];
  const float* bn1  = (const float*)d_in[14];
  const float* Wn2  = (const float*)d_in[15];
  const float* bn2  = (const float*)d_in[16];
  const float* Wc1  = (const float*)d_in[17];
  const float* bc1  = (const float*)d_in[18];
  const float* Wc2  = (const float*)d_in[19];

  cudaFuncSetAttribute(egnn_kernel, cudaFuncAttributeMaxDynamicSharedMemorySize,
                       (int)sizeof(Smem));
  egnn_kernel<<<B, NT, sizeof(Smem)>>>(t, x, h_init, Wemb, bemb, We1, be1, We2, be2,
                                       Watt, batt, Wn1, bn1, Wn2, bn2, Wc1, bc1, Wc2,
                                       (float*)d_out);
}

// round 5
// speedup vs baseline: 1.8119x; 1.0103x over previous
#include <cuda_runtime.h>
#include <cstdint>

namespace {

constexpr int B   = 1024;
constexpr int NP  = 22;
constexpr int DD  = 3;
constexpr int H   = 64;
constexpr int L   = 5;
constexpr int EPB = NP * (NP - 1);   // 462 directed edges per batch
constexpr int ND  = 231;             // dual-edge threads: t handles edges t and t+231
constexpr int HS  = 68;              // h/P/Q stride: 16B-aligned rows
constexpr int MS  = 68;              // m stride: 16B-aligned rows -> LDS/STS.128
constexpr int NT  = 256;

// ---- shared weight region offsets (floats), edge-phase layout ----
constexpr int W_WE1  = 0;            // 130*64 = 8320 (full, for P/Q + rows 128/129)
constexpr int W_WE2  = 8320;         // 64*64  = 4096
constexpr int W_WC1  = 12416;        // 64*64  = 4096
constexpr int W_WATT = 16512;        // 64
constexpr int W_WC2  = 16576;        // 64
constexpr int W_BE1  = 16640;        // 64
constexpr int W_BE2  = 16704;        // 64
constexpr int W_BC1  = 16768;        // 64
constexpr int W_BATT = 16832;        // 1 (+pad)
constexpr int W_SZ   = 16840;
// node-phase overlay
constexpr int W_WN1 = 0;             // 128*64 = 8192
constexpr int W_WN2 = 8192;          // 64*64  = 4096
constexpr int W_BN1 = 12288;
constexpr int W_BN2 = 12352;

struct __align__(16) Smem {
  float W[W_SZ];              //  67,360 B
  float h[NP * HS];           //   5,984 B
  float P[NP * HS];           //   5,984 B  P_i = h_i @ We1[0:64]; reused as agg
  float Q[NP * HS];           //   5,984 B  Q_i = h_i @ We1[64:128]
  float m[EPB * MS];          // 125,664 B  m1 then ungated m2 per edge
  float gate[EPB];            //   1,848 B
  float ea[EPB];              //   1,848 B
  float trans[EPB * DD];      //   5,544 B
  float coord[NP * DD];       //     264 B
  float scr[(NT / 32) * H];   //   2,048 B
};                            // ~222.5 KB

// ---------------- packed f32x2 helpers ----------------
__device__ __forceinline__ unsigned long long splat2(float v) {
  unsigned long long r;
  unsigned int u = __float_as_uint(v);
  asm("mov.b64 %0, {%1, %1};" : "=l"(r) : "r"(u));
  return r;
}
__device__ __forceinline__ unsigned long long pack2(float a, float b) {
  unsigned long long r;
  asm("mov.b64 %0, {%1, %2};" : "=l"(r) : "r"(__float_as_uint(a)), "r"(__float_as_uint(b)));
  return r;
}
__device__ __forceinline__ unsigned long long ffma2(unsigned long long a,
                                                    unsigned long long b,
                                                    unsigned long long c) {
  unsigned long long d;
  asm("fma.rn.f32x2 %0, %1, %2, %3;" : "=l"(d) : "l"(a), "l"(b), "l"(c));
  return d;
}
__device__ __forceinline__ void unpack2(unsigned long long v, float& lo, float& hi) {
  unsigned int a, b;
  asm("mov.b64 {%0, %1}, %2;" : "=r"(a), "=r"(b) : "l"(v));
  lo = __uint_as_float(a);
  hi = __uint_as_float(b);
}
__device__ __forceinline__ float silu_f(float x) {
  return __fdividef(x, 1.0f + __expf(-x));
}

// half-width (32 outputs) k-step, TWO edges: each LDS.128 feeds 4 FFMA2
__device__ __forceinline__ void ghalf2(unsigned long long a0[16],
                                       unsigned long long a1[16],
                                       const ulonglong2* __restrict__ wrow,
                                       unsigned long long in0,
                                       unsigned long long in1) {
#pragma unroll
  for (int i = 0; i < 8; i++) {
    ulonglong2 u = wrow[i];                 // LDS.128 broadcast
    a0[2 * i]     = ffma2(in0, u.x, a0[2 * i]);
    a1[2 * i]     = ffma2(in1, u.x, a1[2 * i]);
    a0[2 * i + 1] = ffma2(in0, u.y, a0[2 * i + 1]);
    a1[2 * i + 1] = ffma2(in1, u.y, a1[2 * i + 1]);
  }
}

// full-width (64 outputs) k-step, TWO edges
__device__ __forceinline__ void gfull2(unsigned long long a0[32],
                                       unsigned long long a1[32],
                                       const ulonglong2* __restrict__ wrow,
                                       unsigned long long in0,
                                       unsigned long long in1) {
#pragma unroll
  for (int i = 0; i < 16; i++) {
    ulonglong2 u = wrow[i];                 // LDS.128 broadcast
    a0[2 * i]     = ffma2(in0, u.x, a0[2 * i]);
    a1[2 * i]     = ffma2(in1, u.x, a1[2 * i]);
    a0[2 * i + 1] = ffma2(in0, u.y, a0[2 * i + 1]);
    a1[2 * i + 1] = ffma2(in1, u.y, a1[2 * i + 1]);
  }
}

__device__ __forceinline__ void cp_f4(float* dst, const float* __restrict__ src,
                                      int nfloats, int tid) {
  float4* d = reinterpret_cast<float4*>(dst);
  const float4* s = reinterpret_cast<const float4*>(src);
  for (int i = tid; i < (nfloats >> 2); i += NT) d[i] = s[i];
}

__global__ void __launch_bounds__(NT, 1)
egnn_kernel(const float* __restrict__ t, const float* __restrict__ x,
            const float* __restrict__ h_init,
            const float* __restrict__ Wemb, const float* __restrict__ bemb,
            const float* __restrict__ We1,  const float* __restrict__ be1,
            const float* __restrict__ We2,  const float* __restrict__ be2,
            const float* __restrict__ Watt, const float* __restrict__ batt,
            const float* __restrict__ Wn1,  const float* __restrict__ bn1,
            const float* __restrict__ Wn2,  const float* __restrict__ bn2,
            const float* __restrict__ Wc1,  const float* __restrict__ bc1,
            const float* __restrict__ Wc2,
            float* __restrict__ out)
{
  extern __shared__ char smem_raw[];
  Smem& s = *reinterpret_cast<Smem*>(smem_raw);
  const int b   = blockIdx.x;
  const int tid = threadIdx.x;

  // ---------- node embedding: h = [one_hot | t] @ Wemb + bemb ----------
  const float tb = t[b];
  for (int task = tid; task < NP * H; task += NT) {
    const int i = task / H, o = task % H;
    float acc = bemb[o] + tb * Wemb[NP * H + o];
#pragma unroll
    for (int j = 0; j < NP; j++) acc += h_init[i * NP + j] * Wemb[j * H + o];
    s.h[i * HS + o] = acc;
  }
  for (int task = tid; task < NP * DD; task += NT)
    s.coord[task] = x[b * (NP * DD) + task];
  __syncthreads();

  // fixed edge attribute from INITIAL coords
  for (int e = tid; e < EPB; e += NT) {
    const int r = e / (NP - 1), jj = e % (NP - 1);
    const int c = jj + (jj >= r ? 1 : 0);
    const float dx = s.coord[r * 3 + 0] - s.coord[c * 3 + 0];
    const float dy = s.coord[r * 3 + 1] - s.coord[c * 3 + 1];
    const float dz = s.coord[r * 3 + 2] - s.coord[c * 3 + 2];
    s.ea[e] = dx * dx + dy * dy + dz * dz;
  }

  for (int l = 0; l < L; l++) {
    // ---------- stage edge-phase weights ----------
    cp_f4(s.W + W_WE1,  We1 + l * 130 * H, 130 * H, tid);
    cp_f4(s.W + W_WE2,  We2 + l * H * H,   H * H,   tid);
    cp_f4(s.W + W_WC1,  Wc1 + l * H * H,   H * H,   tid);
    cp_f4(s.W + W_WATT, Watt + l * H,      H,       tid);
    cp_f4(s.W + W_WC2,  Wc2 + l * H,       H,       tid);
    cp_f4(s.W + W_BE1,  be1 + l * H,       H,       tid);
    cp_f4(s.W + W_BE2,  be2 + l * H,       H,       tid);
    cp_f4(s.W + W_BC1,  bc1 + l * H,       H,       tid);
    if (tid == 0) s.W[W_BATT] = batt[l];
    __syncthreads();

    // ---------- P/Q phase: warp-per-node ----------
    // P_i = h_i @ We1[0:64,:],  Q_i = h_i @ We1[64:128,:]
    {
      const int w = tid >> 5, lane = tid & 31;
      const unsigned long long* W1u =
          reinterpret_cast<const unsigned long long*>(s.W + W_WE1);  // [130][32 pairs]
#pragma unroll 1
      for (int n = w; n < NP; n += NT / 32) {
        const float* hn = s.h + n * HS;
        unsigned long long accP = 0ull, accQ = 0ull;
#pragma unroll 4
        for (int k = 0; k < H; k++) {
          const unsigned long long hv = splat2(hn[k]);
          accP = ffma2(hv, W1u[k * 32 + lane], accP);
          accQ = ffma2(hv, W1u[(H + k) * 32 + lane], accQ);
        }
        reinterpret_cast<unsigned long long*>(s.P + n * HS)[lane] = accP;
        reinterpret_cast<unsigned long long*>(s.Q + n * HS)[lane] = accQ;
      }
    }
    __syncthreads();

    // ---------- edge phase: 2 edges per thread ----------
    if (tid < ND) {
      const int e0 = tid, e1 = tid + ND;
      const int r0 = e0 / (NP - 1), j0 = e0 % (NP - 1);
      const int c0 = j0 + (j0 >= r0 ? 1 : 0);
      const int r1 = e1 / (NP - 1), j1 = e1 % (NP - 1);
      const int c1 = j1 + (j1 >= r1 ? 1 : 0);
      const float dx0 = s.coord[r0 * 3 + 0] - s.coord[c0 * 3 + 0];
      const float dy0 = s.coord[r0 * 3 + 1] - s.coord[c0 * 3 + 1];
      const float dz0 = s.coord[r0 * 3 + 2] - s.coord[c0 * 3 + 2];
      const float dx1 = s.coord[r1 * 3 + 0] - s.coord[c1 * 3 + 0];
      const float dy1 = s.coord[r1 * 3 + 1] - s.coord[c1 * 3 + 1];
      const float dz1 = s.coord[r1 * 3 + 2] - s.coord[c1 * 3 + 2];
      const float rad0 = dx0 * dx0 + dy0 * dy0 + dz0 * dz0;
      const float rad1 = dx1 * dx1 + dy1 * dy1 + dz1 * dz1;
      const float ea0 = s.ea[e0], ea1 = s.ea[e1];
      float* me0 = s.m + e0 * MS;
      float* me1 = s.m + e1 * MS;

      // ---- m1 assembly: m1 = silu(P_r + Q_c + rad*We1[128] + ea*We1[129] + be1) ----
      {
        const float* Pr0 = s.P + r0 * HS;
        const float* Qc0 = s.Q + c0 * HS;
        const float* Pr1 = s.P + r1 * HS;
        const float* Qc1 = s.Q + c1 * HS;
        const float* wr  = s.W + W_WE1 + 128 * H;   // radial row
        const float* we  = s.W + W_WE1 + 129 * H;   // edge-attr row
        const float* bb  = s.W + W_BE1;
#pragma unroll
        for (int o = 0; o < H; o += 4) {
          const float4 p0 = *reinterpret_cast<const float4*>(Pr0 + o);
          const float4 q0 = *reinterpret_cast<const float4*>(Qc0 + o);
          const float4 p1 = *reinterpret_cast<const float4*>(Pr1 + o);
          const float4 q1 = *reinterpret_cast<const float4*>(Qc1 + o);
          const float4 wv = *reinterpret_cast<const float4*>(wr + o);
          const float4 ev = *reinterpret_cast<const float4*>(we + o);
          const float4 bv = *reinterpret_cast<const float4*>(bb + o);
          float4 s0, s1;
          s0.x = silu_f(p0.x + q0.x + rad0 * wv.x + ea0 * ev.x + bv.x);
          s0.y = silu_f(p0.y + q0.y + rad0 * wv.y + ea0 * ev.y + bv.y);
          s0.z = silu_f(p0.z + q0.z + rad0 * wv.z + ea0 * ev.z + bv.z);
          s0.w = silu_f(p0.w + q0.w + rad0 * wv.w + ea0 * ev.w + bv.w);
          s1.x = silu_f(p1.x + q1.x + rad1 * wv.x + ea1 * ev.x + bv.x);
          s1.y = silu_f(p1.y + q1.y + rad1 * wv.y + ea1 * ev.y + bv.y);
          s1.z = silu_f(p1.z + q1.z + rad1 * wv.z + ea1 * ev.z + bv.z);
          s1.w = silu_f(p1.w + q1.w + rad1 * wv.w + ea1 * ev.w + bv.w);
          *reinterpret_cast<float4*>(me0 + o) = s0;   // STS.128
          *reinterpret_cast<float4*>(me1 + o) = s1;
        }
      }

      // ---- GEMV2 (FULL width, k-outer): m2 = silu(m1 @ We2 + be2) ----
      // All m1 reads complete before m2 overwrites the row -> no register stash.
      float att0 = s.W[W_BATT], att1 = att0;
      {
        unsigned long long a0[32], a1[32];
        const unsigned long long* bp =
            reinterpret_cast<const unsigned long long*>(s.W + W_BE2);
#pragma unroll
        for (int i = 0; i < 32; i++) { a0[i] = bp[i]; a1[i] = bp[i]; }
        const ulonglong2* W2 = reinterpret_cast<const ulonglong2*>(s.W + W_WE2);
#pragma unroll 1
        for (int k0 = 0; k0 < H; k0 += 4) {
          const float4 v0 = *reinterpret_cast<const float4*>(me0 + k0);  // LDS.128
          const float4 v1 = *reinterpret_cast<const float4*>(me1 + k0);
          gfull2(a0, a1, W2 + (k0 + 0) * 16, splat2(v0.x), splat2(v1.x));
          gfull2(a0, a1, W2 + (k0 + 1) * 16, splat2(v0.y), splat2(v1.y));
          gfull2(a0, a1, W2 + (k0 + 2) * 16, splat2(v0.z), splat2(v1.z));
          gfull2(a0, a1, W2 + (k0 + 3) * 16, splat2(v0.w), splat2(v1.w));
        }
        // convert: silu, att dot, vectorized store of UNGATED m2
#pragma unroll
        for (int i = 0; i < 16; i++) {
          float p0, q0, p1, q1;
          unpack2(a0[2 * i],     p0, q0);
          unpack2(a0[2 * i + 1], p1, q1);
          p0 = silu_f(p0); q0 = silu_f(q0); p1 = silu_f(p1); q1 = silu_f(q1);
          att0 += p0 * s.W[W_WATT + 4 * i]     + q0 * s.W[W_WATT + 4 * i + 1]
                + p1 * s.W[W_WATT + 4 * i + 2] + q1 * s.W[W_WATT + 4 * i + 3];
          *reinterpret_cast<float4*>(me0 + 4 * i) = make_float4(p0, q0, p1, q1);
        }
#pragma unroll
        for (int i = 0; i < 16; i++) {
          float p0, q0, p1, q1;
          unpack2(a1[2 * i],     p0, q0);
          unpack2(a1[2 * i + 1], p1, q1);
          p0 = silu_f(p0); q0 = silu_f(q0); p1 = silu_f(p1); q1 = silu_f(q1);
          att1 += p0 * s.W[W_WATT + 4 * i]     + q0 * s.W[W_WATT + 4 * i + 1]
                + p1 * s.W[W_WATT + 4 * i + 2] + q1 * s.W[W_WATT + 4 * i + 3];
          *reinterpret_cast<float4*>(me1 + 4 * i) = make_float4(p0, q0, p1, q1);
        }
      }
      const float sg0 = __fdividef(1.0f, 1.0f + __expf(-att0));
      const float sg1 = __fdividef(1.0f, 1.0f + __expf(-att1));
      s.gate[e0] = sg0;
      s.gate[e1] = sg1;

      // ---- GEMVc (half width, dual): phi = silu((m2*sg) @ Wc1 + bc1) . Wc2 ----
      float phi0 = 0.0f, phi1 = 0.0f;
#pragma unroll 1
      for (int half = 0; half < 2; half++) {
        unsigned long long a0[16], a1[16];
        const unsigned long long* bp =
            reinterpret_cast<const unsigned long long*>(s.W + W_BC1) + half * 16;
#pragma unroll
        for (int i = 0; i < 16; i++) { a0[i] = bp[i]; a1[i] = bp[i]; }
        const ulonglong2* Wch =
            reinterpret_cast<const ulonglong2*>(s.W + W_WC1) + half * 8;
#pragma unroll 1
        for (int k0 = 0; k0 < H; k0 += 4) {
          const float4 v0 = *reinterpret_cast<const float4*>(me0 + k0);  // LDS.128
          const float4 v1 = *reinterpret_cast<const float4*>(me1 + k0);
          ghalf2(a0, a1, Wch + (k0 + 0) * 16, splat2(v0.x * sg0), splat2(v1.x * sg1));
          ghalf2(a0, a1, Wch + (k0 + 1) * 16, splat2(v0.y * sg0), splat2(v1.y * sg1));
          ghalf2(a0, a1, Wch + (k0 + 2) * 16, splat2(v0.z * sg0), splat2(v1.z * sg1));
          ghalf2(a0, a1, Wch + (k0 + 3) * 16, splat2(v0.w * sg0), splat2(v1.w * sg1));
        }
#pragma unroll
        for (int i = 0; i < 16; i++) {
          float p, q;
          unpack2(a0[i], p, q);
          phi0 += silu_f(p) * s.W[W_WC2 + half * 32 + 2 * i]
                + silu_f(q) * s.W[W_WC2 + half * 32 + 2 * i + 1];
          unpack2(a1[i], p, q);
          phi1 += silu_f(p) * s.W[W_WC2 + half * 32 + 2 * i]
                + silu_f(q) * s.W[W_WC2 + half * 32 + 2 * i + 1];
        }
      }
      const float th0 = tanhf(phi0) * 3.0f;   // COORDS_RANGE
      const float th1 = tanhf(phi1) * 3.0f;
      s.trans[e0 * 3 + 0] = dx0 * th0;
      s.trans[e0 * 3 + 1] = dy0 * th0;
      s.trans[e0 * 3 + 2] = dz0 * th0;
      s.trans[e1 * 3 + 0] = dx1 * th1;
      s.trans[e1 * 3 + 1] = dy1 * th1;
      s.trans[e1 * 3 + 2] = dz1 * th1;
    }
    __syncthreads();

    // ---------- stage node weights (overlay) + gated segment-sum ----------
    cp_f4(s.W + W_WN1, Wn1 + l * 128 * H, 128 * H, tid);
    cp_f4(s.W + W_WN2, Wn2 + l * H * H,   H * H,   tid);
    cp_f4(s.W + W_BN1, bn1 + l * H,       H,       tid);
    cp_f4(s.W + W_BN2, bn2 + l * H,       H,       tid);
    for (int task = tid; task < NP * H; task += NT) {
      const int r = task / H, o = task % H;
      const float* mp = s.m + (r * (NP - 1)) * MS + o;
      const float* gp = s.gate + r * (NP - 1);
      float a = 0.0f;
#pragma unroll
      for (int j = 0; j < NP - 1; j++) a = fmaf(gp[j], mp[j * MS], a);
      s.P[r * HS + o] = a;                  // agg (reuses P buffer)
    }
    for (int task = tid; task < NP * DD; task += NT) {
      const int r = task / DD, d = task % DD;
      const float* tp = s.trans + (r * (NP - 1)) * DD + d;
      float a = 0.0f;
#pragma unroll
      for (int j = 0; j < NP - 1; j++) a += tp[j * DD];
      s.coord[task] += a;
    }
    __syncthreads();

    // ---------- node phase: warp-per-node, h += MLP([h | agg]) ----------
    {
      const int w = tid >> 5, lane = tid & 31;
      const unsigned long long* Wn1u =
          reinterpret_cast<const unsigned long long*>(s.W + W_WN1);
      const unsigned long long* Wn2u =
          reinterpret_cast<const unsigned long long*>(s.W + W_WN2);
      const unsigned long long bn1p =
          reinterpret_cast<const unsigned long long*>(s.W + W_BN1)[lane];
      const unsigned long long bn2p =
          reinterpret_cast<const unsigned long long*>(s.W + W_BN2)[lane];
      unsigned long long* scru = reinterpret_cast<unsigned long long*>(s.scr);
#pragma unroll 1
      for (int n = w; n < NP; n += NT / 32) {
        const float* hn = s.h + n * HS;
        const float* an = s.P + n * HS;     // agg
        unsigned long long a1 = bn1p;
#pragma unroll 2
        for (int k = 0; k < H; k++) a1 = ffma2(splat2(hn[k]), Wn1u[k * 32 + lane], a1);
#pragma unroll 2
        for (int k = 0; k < H; k++) a1 = ffma2(splat2(an[k]), Wn1u[(H + k) * 32 + lane], a1);
        float lo, hi; unpack2(a1, lo, hi);
        scru[w * 32 + lane] = pack2(silu_f(lo), silu_f(hi));
        __syncwarp();
        const float* sc = s.scr + w * H;
        unsigned long long a2 = bn2p;
#pragma unroll 2
        for (int k = 0; k < H; k++) a2 = ffma2(splat2(sc[k]), Wn2u[k * 32 + lane], a2);
        unpack2(a2, lo, hi);
        s.h[n * HS + 2 * lane]     += lo;
        s.h[n * HS + 2 * lane + 1] += hi;
        __syncwarp();
      }
    }
    __syncthreads();
  }

  // ---------- output: vel = (coord - x) - mean_over_particles ----------
  if (tid < DD) {
    float mm = 0.0f;
    for (int i = 0; i < NP; i++)
      mm += s.coord[i * DD + tid] - x[b * (NP * DD) + i * DD + tid];
    s.ea[tid] = mm * (1.0f / NP);
  }
  __syncthreads();
  for (int task = tid; task < NP * DD; task += NT) {
    out[b * (NP * DD) + task] =
        (s.coord[task] - x[b * (NP * DD) + task]) - s.ea[task % DD];
  }
}

}  // namespace

extern "C" void kernel_launch(void* const* d_in, const int* in_sizes, int n_in,
                              void* d_out, int out_size) {
  (void)in_sizes; (void)n_in; (void)out_size;
  const float* t      = (const float*)d_in[0];
  const float* x      = (const float*)d_in[1];
  const float* h_init = (const float*)d_in[2];
  // d_in[3] rows / d_in[4] cols: fixed fully-connected pattern, derived analytically
  const float* Wemb = (const float*)d_in[5];
  const float* bemb = (const float*)d_in[6];
  const float* We1  = (const float*)d_in[7];
  const float* be1  = (const float*)d_in[8];
  const float* We2  = (const float*)d_in[9];
  const float* be2  = (const float*)d_in[10];
  const float* Watt = (const float*)d_in[11];
  const float* batt = (const float*)d_in[12];
  const float* Wn1  = (const float*)d_in[13];
  const float* bn1  = (const float*)d_in[14];
  const float* Wn2  = (const float*)d_in[15];
  const float* bn2  = (const float*)d_in[16];
  const float* Wc1  = (const float*)d_in[17];
  const float* bc1  = (const float*)d_in[18];
  const float* Wc2  = (const float*)d_in[19];

  cudaFuncSetAttribute(egnn_kernel, cudaFuncAttributeMaxDynamicSharedMemorySize,
                       (int)sizeof(Smem));
  egnn_kernel<<<B, NT, sizeof(Smem)>>>(t, x, h_init, Wemb, bemb, We1, be1, We2, be2,
                                       Watt, batt, Wn1, bn1, Wn2, bn2, Wc1, bc1, Wc2,
                                       (float*)d_out);
}